// round 2
// baseline (speedup 1.0000x reference)
#include <cuda_runtime.h>

// Problem constants
#define BB   2
#define TT   2048
#define CCH  1024
#define HH   16
#define HDIM 64
#define NTOK (BB * TT)     // 4096
#define C3   (3 * CCH)     // 3072

// Scratch (allocation-free rule: __device__ globals)
__device__ float g_qkv[(size_t)NTOK * C3];   // [4096, 3072]  q|k|v per token
__device__ float g_att[(size_t)NTOK * CCH];  // [4096, 1024]  attention output pre-Wo

// ---------------------------------------------------------------------------
// Classic fp32 SGEMM: C[M,N] = A[M,K] @ B[K,N] + bias[N]
// BM=BN=128, BK=8, 256 threads, 8x8 microtile per thread.
// All dims divisible by tiles for this problem (no bounds checks).
// ---------------------------------------------------------------------------
__global__ void __launch_bounds__(256) sgemm_bias(
    const float* __restrict__ A, const float* __restrict__ B,
    const float* __restrict__ bias, float* __restrict__ C,
    int N, int K)
{
    __shared__ float As[8][132];   // padded to kill store conflicts
    __shared__ float Bs[8][128];

    const int tid = threadIdx.x;
    const int tx  = tid & 15;
    const int ty  = tid >> 4;
    const int row0 = blockIdx.y * 128;
    const int col0 = blockIdx.x * 128;

    // A tile load: 128 rows x 8 k, each thread one float4
    const int arow = tid >> 1;
    const int acol = (tid & 1) * 4;
    // B tile load: 8 k-rows x 128 cols, each thread one float4
    const int brow = tid >> 5;
    const int bcol = (tid & 31) * 4;

    const float* Aptr = A + (size_t)(row0 + arow) * K + acol;
    const float* Bptr = B + (size_t)brow * N + col0 + bcol;

    float acc[8][8];
#pragma unroll
    for (int i = 0; i < 8; i++)
#pragma unroll
        for (int j = 0; j < 8; j++) acc[i][j] = 0.f;

    for (int k0 = 0; k0 < K; k0 += 8) {
        float4 av = *(const float4*)(Aptr + k0);
        As[acol + 0][arow] = av.x;
        As[acol + 1][arow] = av.y;
        As[acol + 2][arow] = av.z;
        As[acol + 3][arow] = av.w;
        float4 bv = *(const float4*)(Bptr + (size_t)k0 * N);
        *(float4*)&Bs[brow][bcol] = bv;
        __syncthreads();

#pragma unroll
        for (int k = 0; k < 8; k++) {
            float a[8], b[8];
#pragma unroll
            for (int i = 0; i < 8; i++) a[i] = As[k][ty * 8 + i];
#pragma unroll
            for (int j = 0; j < 8; j++) b[j] = Bs[k][tx * 8 + j];
#pragma unroll
            for (int i = 0; i < 8; i++)
#pragma unroll
                for (int j = 0; j < 8; j++)
                    acc[i][j] += a[i] * b[j];
        }
        __syncthreads();
    }

    const int crow = row0 + ty * 8;
    const int ccol = col0 + tx * 8;
    float bb[8];
#pragma unroll
    for (int j = 0; j < 8; j++) bb[j] = bias[ccol + j];

#pragma unroll
    for (int i = 0; i < 8; i++) {
        float4 o1, o2;
        o1.x = acc[i][0] + bb[0]; o1.y = acc[i][1] + bb[1];
        o1.z = acc[i][2] + bb[2]; o1.w = acc[i][3] + bb[3];
        o2.x = acc[i][4] + bb[4]; o2.y = acc[i][5] + bb[5];
        o2.z = acc[i][6] + bb[6]; o2.w = acc[i][7] + bb[7];
        *(float4*)&C[(size_t)(crow + i) * N + ccol]     = o1;
        *(float4*)&C[(size_t)(crow + i) * N + ccol + 4] = o2;
    }
}

// ---------------------------------------------------------------------------
// Flash-attention style causal MHA, fp32.
// Block: 128 threads, each thread owns one query row (q + O accumulator in
// registers). K/V tiles of 32 rows staged in smem, broadcast LDS reads.
// Grid: (T/128, B*H).
// qkv layout: [tok, 3C] with q at +0, k at +C, v at +2C; head h at +h*64.
// ---------------------------------------------------------------------------
__global__ void __launch_bounds__(128) attn_fwd(
    const float* __restrict__ qkv, float* __restrict__ out)
{
    const int bh = blockIdx.y;
    const int b = bh >> 4;       // / HH
    const int h = bh & 15;       // % HH
    const int qbase = blockIdx.x * 128;
    const int row = qbase + threadIdx.x;

    const float* qptr = qkv + (size_t)(b * TT + row) * C3 + h * HDIM;
    float4 q[16];
#pragma unroll
    for (int d = 0; d < 16; d++) q[d] = ((const float4*)qptr)[d];

    float4 o[16];
#pragma unroll
    for (int d = 0; d < 16; d++) o[d] = make_float4(0.f, 0.f, 0.f, 0.f);
    float m = -1e30f, l = 0.f;

    __shared__ float4 ks[32][16];
    __shared__ float4 vs[32][16];

    const int ntiles = (qbase + 128) >> 5;   // causal: only tiles kv0 < qbase+128
    const float scale = 0.125f;              // 1/sqrt(64)

    for (int t = 0; t < ntiles; t++) {
        const int kv0 = t * 32;
        // cooperative K/V tile load: 32 rows x 16 float4 = 512 float4 each
#pragma unroll
        for (int i = 0; i < 4; i++) {
            int idx = threadIdx.x + i * 128;
            int r = idx >> 4, c = idx & 15;
            const float* kp = qkv + (size_t)(b * TT + kv0 + r) * C3 + CCH + h * HDIM;
            ks[r][c] = ((const float4*)kp)[c];
            vs[r][c] = ((const float4*)(kp + CCH))[c];
        }
        __syncthreads();

        float s[32];
        const int kmax = row - kv0;   // allowed: j <= kmax
#pragma unroll
        for (int j = 0; j < 32; j++) {
            float ax = 0.f, ay = 0.f, az = 0.f, aw = 0.f;
#pragma unroll
            for (int d = 0; d < 16; d++) {
                float4 kk = ks[j][d];
                ax += q[d].x * kk.x;
                ay += q[d].y * kk.y;
                az += q[d].z * kk.z;
                aw += q[d].w * kk.w;
            }
            float sv = (ax + ay) + (az + aw);
            s[j] = (j <= kmax) ? sv * scale : -1e30f;
        }

        float mt = m;
#pragma unroll
        for (int j = 0; j < 32; j++) mt = fmaxf(mt, s[j]);
        const float corr = __expf(m - mt);
        m = mt;
        l *= corr;
#pragma unroll
        for (int d = 0; d < 16; d++) {
            o[d].x *= corr; o[d].y *= corr; o[d].z *= corr; o[d].w *= corr;
        }
#pragma unroll
        for (int j = 0; j < 32; j++) {
            const float p = __expf(s[j] - mt);
            l += p;
#pragma unroll
            for (int d = 0; d < 16; d++) {
                float4 vv = vs[j][d];
                o[d].x += p * vv.x;
                o[d].y += p * vv.y;
                o[d].z += p * vv.z;
                o[d].w += p * vv.w;
            }
        }
        __syncthreads();
    }

    const float inv = 1.f / l;
    float* op = out + (size_t)(b * TT + row) * CCH + h * HDIM;
#pragma unroll
    for (int d = 0; d < 16; d++) {
        float4 ov = o[d];
        ov.x *= inv; ov.y *= inv; ov.z *= inv; ov.w *= inv;
        ((float4*)op)[d] = ov;
    }
}

// ---------------------------------------------------------------------------
extern "C" void kernel_launch(void* const* d_in, const int* in_sizes, int n_in,
                              void* d_out, int out_size)
{
    (void)in_sizes; (void)n_in; (void)out_size;
    const float* x    = (const float*)d_in[0];
    const float* Wqkv = (const float*)d_in[1];
    const float* bqkv = (const float*)d_in[2];
    const float* Wo   = (const float*)d_in[3];
    const float* bo   = (const float*)d_in[4];
    float* out = (float*)d_out;

    float* qkvbuf = nullptr;
    float* attbuf = nullptr;
    cudaGetSymbolAddress((void**)&qkvbuf, g_qkv);
    cudaGetSymbolAddress((void**)&attbuf, g_att);

    // 1) QKV projection: [4096,1024] @ [1024,3072] + bqkv
    sgemm_bias<<<dim3(C3 / 128, NTOK / 128), 256>>>(x, Wqkv, bqkv, qkvbuf, C3, CCH);

    // 2) Causal flash attention per (b,h), writes [4096,1024]
    attn_fwd<<<dim3(TT / 128, BB * HH), 128>>>(qkvbuf, attbuf);

    // 3) Output projection: [4096,1024] @ [1024,1024] + bo
    sgemm_bias<<<dim3(CCH / 128, NTOK / 128), 256>>>(attbuf, Wo, bo, out, CCH, CCH);
}

// round 7
// speedup vs baseline: 1.1749x; 1.1749x over previous
#include <cuda_runtime.h>
#include <cstdint>

// Problem constants
#define BB   2
#define TT   2048
#define CCH  1024
#define HH   16
#define HDIM 64
#define NTOK (BB * TT)     // 4096
#define C3   (3 * CCH)     // 3072

// Scratch (allocation-free rule: __device__ globals)
__device__ float g_qkv[(size_t)NTOK * C3];    // [4096, 3072]
__device__ float g_att[(size_t)NTOK * CCH];   // [4096, 1024]
__device__ float g_wqkvT[(size_t)C3 * CCH];   // Wqkv^T [3072,1024]
__device__ float g_woT[(size_t)CCH * CCH];    // Wo^T   [1024,1024]

// ---------------------------------------------------------------------------
// helpers
// ---------------------------------------------------------------------------
__device__ __forceinline__ uint32_t smem_u32(const void* p) {
    uint32_t a;
    asm("{ .reg .u64 t; cvta.to.shared.u64 t, %1; cvt.u32.u64 %0, t; }" : "=r"(a) : "l"(p));
    return a;
}

__device__ __forceinline__ void cp_async16(uint32_t saddr, const void* gaddr) {
    asm volatile("cp.async.ca.shared.global [%0], [%1], 16;" :: "r"(saddr), "l"(gaddr) : "memory");
}
#define CP_COMMIT() asm volatile("cp.async.commit_group;" ::: "memory")
#define CP_WAIT(n)  asm volatile("cp.async.wait_group %0;" :: "n"(n) : "memory")

__device__ __forceinline__ void mma_tf32(float* c, const uint32_t* a, const uint32_t* b) {
    asm volatile(
        "mma.sync.aligned.m16n8k8.row.col.f32.tf32.tf32.f32 "
        "{%0,%1,%2,%3}, {%4,%5,%6,%7}, {%8,%9}, {%0,%1,%2,%3};"
        : "+f"(c[0]), "+f"(c[1]), "+f"(c[2]), "+f"(c[3])
        : "r"(a[0]), "r"(a[1]), "r"(a[2]), "r"(a[3]), "r"(b[0]), "r"(b[1]));
}

// round-to-nearest fp32 -> tf32 (result stored as fp32 bits with low mantissa zero)
__device__ __forceinline__ uint32_t f2tf(float x) {
    uint32_t r;
    asm("cvt.rna.tf32.f32 %0, %1;" : "=r"(r) : "f"(x));
    return r;
}
// split x into (hi, lo) tf32 pair: x ~= hi + lo
__device__ __forceinline__ void tf32_split(float x, uint32_t& hi, uint32_t& lo) {
    hi = f2tf(x);
    lo = f2tf(x - __uint_as_float(hi));
}

// ---------------------------------------------------------------------------
// 32x32 tiled transpose: out[c][r] = in[r][c].  grid (Cc/32, R/32), block (32,8)
// ---------------------------------------------------------------------------
__global__ void __launch_bounds__(256) transpose_k(
    const float* __restrict__ in, float* __restrict__ out, int R, int Cc)
{
    __shared__ float t[32][33];
    const int c0 = blockIdx.x * 32, r0 = blockIdx.y * 32;
    const int x = threadIdx.x, y = threadIdx.y;
#pragma unroll
    for (int i = 0; i < 32; i += 8)
        t[y + i][x] = in[(size_t)(r0 + y + i) * Cc + c0 + x];
    __syncthreads();
#pragma unroll
    for (int i = 0; i < 32; i += 8)
        out[(size_t)(c0 + y + i) * R + r0 + x] = t[x][y + i];
}

// ---------------------------------------------------------------------------
// 3xTF32 warp-MMA GEMM: C[M,N] = A[M,K] @ BT[N,K]^T + bias[N]
// CTA tile 128x128x32, 256 threads = 8 warps in 2(m) x 4(n), warp tile 64x32.
// cp.async double-buffered smem, pitch-36 rows (conflict-free frag loads).
// Each fp32 operand split hi/lo tf32; c += ahi*bhi + ahi*blo + alo*bhi.
// grid: (N/128, M/128)
// ---------------------------------------------------------------------------
#define PITCH 36                       // floats per smem row (144B, 16B aligned)
#define STG_BYTES (128 * PITCH * 4)    // 18432 per operand per stage
#define SMEM_GEMM (4 * STG_BYTES)      // 73728

__global__ void __launch_bounds__(256) gemm_mma(
    const float* __restrict__ A, const float* __restrict__ BT,
    const float* __restrict__ bias, float* __restrict__ C,
    int N, int K)
{
    extern __shared__ char smem[];
    float* As[2] = { (float*)smem,                   (float*)(smem + 2 * STG_BYTES) };
    float* Bs[2] = { (float*)(smem + STG_BYTES),     (float*)(smem + 3 * STG_BYTES) };
    const uint32_t sAu[2] = { smem_u32(As[0]), smem_u32(As[1]) };
    const uint32_t sBu[2] = { smem_u32(Bs[0]), smem_u32(Bs[1]) };

    const int tid = threadIdx.x;
    const int lane = tid & 31;
    const int wid = tid >> 5;
    const int wm = (wid & 1) * 64;     // warp m offset
    const int wn = (wid >> 1) * 32;    // warp n offset
    const int g = lane >> 2;           // group id 0..7
    const int t = lane & 3;            // thread-in-group 0..3

    const int row0 = blockIdx.y * 128;
    const int col0 = blockIdx.x * 128;

    const int ldrow = tid >> 3;        // 0..31 (x4 passes -> 128 rows)
    const int ldc4  = tid & 7;         // float4 index in 32-float row

    float c[4][4][4];
#pragma unroll
    for (int mf = 0; mf < 4; mf++)
#pragma unroll
        for (int nf = 0; nf < 4; nf++)
#pragma unroll
            for (int i = 0; i < 4; i++) c[mf][nf][i] = 0.f;

    const int niter = K / 32;

    // --- stage loader ---
#define LOAD_STAGE(it, buf)                                                     \
    {                                                                           \
        const int k0_ = (it) * 32;                                              \
        _Pragma("unroll")                                                       \
        for (int i = 0; i < 4; i++) {                                           \
            const int r = ldrow + i * 32;                                       \
            const uint32_t so = (uint32_t)(r * PITCH + ldc4 * 4) * 4;           \
            cp_async16(sAu[buf] + so, A  + (size_t)(row0 + r) * K + k0_ + ldc4 * 4); \
            cp_async16(sBu[buf] + so, BT + (size_t)(col0 + r) * K + k0_ + ldc4 * 4); \
        }                                                                       \
        CP_COMMIT();                                                            \
    }

    LOAD_STAGE(0, 0);
    LOAD_STAGE(1, 1);
    CP_WAIT(1);
    __syncthreads();

    for (int it = 0; it < niter; it++) {
        const int buf = it & 1;
        const float* Ab = As[buf];
        const float* Bb = Bs[buf];

#pragma unroll
        for (int ks = 0; ks < 4; ks++) {
            const int k = ks * 8 + t;
            uint32_t ah[4][4], al[4][4], bh[4][2], bl[4][2];
#pragma unroll
            for (int mf = 0; mf < 4; mf++) {
                const int base = (wm + mf * 16 + g) * PITCH + k;
                tf32_split(Ab[base],                 ah[mf][0], al[mf][0]);
                tf32_split(Ab[base + 8 * PITCH],     ah[mf][1], al[mf][1]);
                tf32_split(Ab[base + 4],             ah[mf][2], al[mf][2]);
                tf32_split(Ab[base + 8 * PITCH + 4], ah[mf][3], al[mf][3]);
            }
#pragma unroll
            for (int nf = 0; nf < 4; nf++) {
                const int base = (wn + nf * 8 + g) * PITCH + k;
                tf32_split(Bb[base],     bh[nf][0], bl[nf][0]);
                tf32_split(Bb[base + 4], bh[nf][1], bl[nf][1]);
            }
#pragma unroll
            for (int mf = 0; mf < 4; mf++)
#pragma unroll
                for (int nf = 0; nf < 4; nf++) {
                    mma_tf32(c[mf][nf], al[mf], bh[nf]);   // lo*hi
                    mma_tf32(c[mf][nf], ah[mf], bl[nf]);   // hi*lo
                    mma_tf32(c[mf][nf], ah[mf], bh[nf]);   // hi*hi (last: largest term)
                }
        }

        __syncthreads();
        if (it + 2 < niter) {
            LOAD_STAGE(it + 2, buf);
            CP_WAIT(1);
        } else {
            CP_WAIT(0);
        }
        __syncthreads();
    }
#undef LOAD_STAGE

    // epilogue: c0:(g,2t) c1:(g,2t+1) c2:(g+8,2t) c3:(g+8,2t+1)
#pragma unroll
    for (int mf = 0; mf < 4; mf++) {
        const int r0_ = row0 + wm + mf * 16 + g;
#pragma unroll
        for (int nf = 0; nf < 4; nf++) {
            const int cc = col0 + wn + nf * 8 + t * 2;
            const float b0 = bias[cc], b1 = bias[cc + 1];
            float2 lo = make_float2(c[mf][nf][0] + b0, c[mf][nf][1] + b1);
            float2 hi = make_float2(c[mf][nf][2] + b0, c[mf][nf][3] + b1);
            *(float2*)&C[(size_t)r0_ * N + cc]       = lo;
            *(float2*)&C[(size_t)(r0_ + 8) * N + cc] = hi;
        }
    }
}

// ---------------------------------------------------------------------------
// Flash-attention style causal MHA, fp32 (unchanged — R7 target)
// ---------------------------------------------------------------------------
__global__ void __launch_bounds__(128) attn_fwd(
    const float* __restrict__ qkv, float* __restrict__ out)
{
    const int bh = blockIdx.y;
    const int b = bh >> 4;
    const int h = bh & 15;
    const int qbase = blockIdx.x * 128;
    const int row = qbase + threadIdx.x;

    const float* qptr = qkv + (size_t)(b * TT + row) * C3 + h * HDIM;
    float4 q[16];
#pragma unroll
    for (int d = 0; d < 16; d++) q[d] = ((const float4*)qptr)[d];

    float4 o[16];
#pragma unroll
    for (int d = 0; d < 16; d++) o[d] = make_float4(0.f, 0.f, 0.f, 0.f);
    float m = -1e30f, l = 0.f;

    __shared__ float4 ks[32][16];
    __shared__ float4 vs[32][16];

    const int ntiles = (qbase + 128) >> 5;
    const float scale = 0.125f;

    for (int tt = 0; tt < ntiles; tt++) {
        const int kv0 = tt * 32;
#pragma unroll
        for (int i = 0; i < 4; i++) {
            int idx = threadIdx.x + i * 128;
            int r = idx >> 4, cc = idx & 15;
            const float* kp = qkv + (size_t)(b * TT + kv0 + r) * C3 + CCH + h * HDIM;
            ks[r][cc] = ((const float4*)kp)[cc];
            vs[r][cc] = ((const float4*)(kp + CCH))[cc];
        }
        __syncthreads();

        float s[32];
        const int kmax = row - kv0;
#pragma unroll
        for (int j = 0; j < 32; j++) {
            float ax = 0.f, ay = 0.f, az = 0.f, aw = 0.f;
#pragma unroll
            for (int d = 0; d < 16; d++) {
                float4 kk = ks[j][d];
                ax += q[d].x * kk.x;
                ay += q[d].y * kk.y;
                az += q[d].z * kk.z;
                aw += q[d].w * kk.w;
            }
            float sv = (ax + ay) + (az + aw);
            s[j] = (j <= kmax) ? sv * scale : -1e30f;
        }

        float mt = m;
#pragma unroll
        for (int j = 0; j < 32; j++) mt = fmaxf(mt, s[j]);
        const float corr = __expf(m - mt);
        m = mt;
        l *= corr;
#pragma unroll
        for (int d = 0; d < 16; d++) {
            o[d].x *= corr; o[d].y *= corr; o[d].z *= corr; o[d].w *= corr;
        }
#pragma unroll
        for (int j = 0; j < 32; j++) {
            const float p = __expf(s[j] - mt);
            l += p;
#pragma unroll
            for (int d = 0; d < 16; d++) {
                float4 vv = vs[j][d];
                o[d].x += p * vv.x;
                o[d].y += p * vv.y;
                o[d].z += p * vv.z;
                o[d].w += p * vv.w;
            }
        }
        __syncthreads();
    }

    const float inv = 1.f / l;
    float* op = out + (size_t)(b * TT + row) * CCH + h * HDIM;
#pragma unroll
    for (int d = 0; d < 16; d++) {
        float4 ov = o[d];
        ov.x *= inv; ov.y *= inv; ov.z *= inv; ov.w *= inv;
        ((float4*)op)[d] = ov;
    }
}

// ---------------------------------------------------------------------------
extern "C" void kernel_launch(void* const* d_in, const int* in_sizes, int n_in,
                              void* d_out, int out_size)
{
    (void)in_sizes; (void)n_in; (void)out_size;
    const float* x    = (const float*)d_in[0];
    const float* Wqkv = (const float*)d_in[1];
    const float* bqkv = (const float*)d_in[2];
    const float* Wo   = (const float*)d_in[3];
    const float* bo   = (const float*)d_in[4];
    float* out = (float*)d_out;

    float *qkvbuf, *attbuf, *wqkvT, *woT;
    cudaGetSymbolAddress((void**)&qkvbuf, g_qkv);
    cudaGetSymbolAddress((void**)&attbuf, g_att);
    cudaGetSymbolAddress((void**)&wqkvT, g_wqkvT);
    cudaGetSymbolAddress((void**)&woT, g_woT);

    static int smem_set = 0;
    if (!smem_set) {
        cudaFuncSetAttribute(gemm_mma, cudaFuncAttributeMaxDynamicSharedMemorySize, SMEM_GEMM);
        smem_set = 1;
    }

    // 0) transpose weights -> col-major B operands
    transpose_k<<<dim3(C3 / 32, CCH / 32), dim3(32, 8)>>>(Wqkv, wqkvT, CCH, C3);
    transpose_k<<<dim3(CCH / 32, CCH / 32), dim3(32, 8)>>>(Wo, woT, CCH, CCH);

    // 1) QKV projection (3xTF32 warp MMA)
    gemm_mma<<<dim3(C3 / 128, NTOK / 128), 256, SMEM_GEMM>>>(x, wqkvT, bqkv, qkvbuf, C3, CCH);

    // 2) causal flash attention (fp32)
    attn_fwd<<<dim3(TT / 128, BB * HH), 128>>>(qkvbuf, attbuf);

    // 3) output projection (3xTF32 warp MMA)
    gemm_mma<<<dim3(CCH / 128, NTOK / 128), 256, SMEM_GEMM>>>(attbuf, woT, bo, out, CCH, CCH);
}